// round 14
// baseline (speedup 1.0000x reference)
#include <cuda_runtime.h>
#include <cuda_fp16.h>
#include <cstdint>

#define N 8192
#define D 128
#define NBLK 64               // 64 tiles of 128 rows/cols
#define TILEB 32768           // one 128x128 fp16 tile, bytes
#define NCTA 2080             // upper-triangle tile pairs (64*65/2)
#define EPS2 0.25f
#define TENLOG2E 14.426950408889634f

// ---------------- device scratch ----------------
__device__ uint4  g_hf[NBLK * 2048];   // fp16 tiles, ldmatrix-swizzled
__device__ float4 g_pos4[N];           // (x,y,z,|p|^2)
__device__ float  g_dse[NCTA * 128], g_dsp[NCTA * 128], g_dct[NCTA * 128];  // row (block I) partials
__device__ float  g_tse[NCTA * 128], g_tsp[NCTA * 128], g_tct[NCTA * 128];  // col (block J) partials
__device__ float  g_partL[256], g_partV[256];
__device__ int    g_done;
__device__ int    g_tick;              // monotonic ticket-barrier counter (never reset)

// ---------------- portable PTX helpers ----------------
#define CP16(dst, src) \
    asm volatile("cp.async.cg.shared.global [%0], [%1], 16;\n" :: "r"(dst), "l"(src) : "memory")
#define CP_COMMIT() asm volatile("cp.async.commit_group;\n" ::: "memory")
#define CP_WAIT0()  asm volatile("cp.async.wait_group 0;\n" ::: "memory")

#define LDSM4(r0, r1, r2, r3, addr) \
    asm volatile("ldmatrix.sync.aligned.m8n8.x4.shared.b16 {%0,%1,%2,%3}, [%4];" \
                 : "=r"(r0), "=r"(r1), "=r"(r2), "=r"(r3) : "r"(addr))

#define MMA16816(d, a, b0, b1) \
    asm volatile("mma.sync.aligned.m16n8k16.row.col.f32.f16.f16.f32 " \
                 "{%0,%1,%2,%3}, {%4,%5,%6,%7}, {%8,%9}, {%0,%1,%2,%3};" \
                 : "+f"((d)[0]), "+f"((d)[1]), "+f"((d)[2]), "+f"((d)[3]) \
                 : "r"((a)[0]), "r"((a)[1]), "r"((a)[2]), "r"((a)[3]), "r"(b0), "r"(b1))

#define PACK2(out, lo, hi) asm("mov.b64 %0, {%1, %2};" : "=l"(out) : "f"(lo), "f"(hi))
#define UNPACK2(lo, hi, in) asm("mov.b64 {%0, %1}, %2;" : "=f"(lo), "=f"(hi) : "l"(in))
#define ADD2(c, a) asm("add.rn.f32x2 %0, %0, %1;" : "+l"(c) : "l"(a))
#define EX2(e, arg) asm("ex2.approx.ftz.f32 %0, %1;" : "=f"(e) : "f"(arg))

__device__ __host__ __forceinline__ uint32_t swz(uint32_t x, uint32_t c16) {
    return (c16 & 8u) | ((c16 & 7u) ^ x);
}

__device__ __forceinline__ int tri_base(int I) { return I * NBLK - (I * (I - 1)) / 2; }

// Replay-safe ticket barrier: each instance consumes gridDim.x increments of the
// monotonic counter. All CTAs are resident (grid = 2 x SMs, occ-2 guaranteed by
// launch_bounds + smem), so spinning is deadlock-free.
__device__ __forceinline__ void grid_barrier(int tid) {
    __syncthreads();
    if (tid == 0) {
        __threadfence();
        int t = atomicAdd(&g_tick, 1);
        int target = (t / (int)gridDim.x + 1) * (int)gridDim.x;
        while (*(volatile int*)&g_tick < target) __nanosleep(64);
    }
    __syncthreads();
}

// smem: A 0..32K | B buf0 32K..64K | B buf1 64K..96K | red @96K (9216 B)
#define ASM 0
#define BBUF(b) (32768 + (b) * 32768)
#define RED 98304
#define SMEM_REQ (RED + 9216)   // 107520

__device__ __forceinline__ void load_tile16(uint32_t dst, int blk, int tid) {
    const char* gh = (const char*)g_hf + (size_t)blk * TILEB;
    #pragma unroll
    for (int i = 0; i < 8; i++) {
        uint32_t o = (uint32_t)(tid * 128 + i * 16);
        CP16(dst + o, gh + o);
    }
}

__global__ void __launch_bounds__(256, 2) fused_kernel(
    const float* __restrict__ h, const float* __restrict__ pos, float* __restrict__ out) {
    extern __shared__ __align__(128) char smem[];
    const uint32_t sbase = (uint32_t)__cvta_generic_to_shared(smem);
    float* rbuf_se = (float*)(smem + RED);
    float* rbuf_sp = rbuf_se + 512;
    float* rbuf_ct = rbuf_sp + 512;
    float* cbuf_se = rbuf_ct + 512;
    float* cbuf_sp = cbuf_se + 256;
    float* cbuf_ct = cbuf_sp + 256;

    const int tid = threadIdx.x, wid = tid >> 5, lane = tid & 31;
    const int warpRow = wid >> 2, warpCol = wid & 3;
    const int G = (int)gridDim.x;

    // ================= phase 0: normalize + fp16 + swizzle + pos pack =================
    if (blockIdx.x == 0 && tid == 0) g_done = 0;
    {
        int r0 = (int)((long long)blockIdx.x * N / G);
        int r1 = (int)((long long)(blockIdx.x + 1) * N / G);
        for (int row = r0 + wid; row < r1; row += 8) {
            float4 v = ((const float4*)h)[row * 32 + lane];
            float ss = v.x * v.x + v.y * v.y + v.z * v.z + v.w * v.w;
            #pragma unroll
            for (int o = 16; o; o >>= 1) ss += __shfl_xor_sync(0xffffffffu, ss, o);
            float inv = 1.0f / fmaxf(sqrtf(ss), 1e-12f);
            float x[4] = {v.x * inv, v.y * inv, v.z * inv, v.w * inv};
            unsigned short hb[4];
            #pragma unroll
            for (int j = 0; j < 4; j++) hb[j] = __half_as_ushort(__float2half_rn(x[j]));
            uint2 hu = make_uint2((uint32_t)hb[0] | ((uint32_t)hb[1] << 16),
                                  (uint32_t)hb[2] | ((uint32_t)hb[3] << 16));
            int blk = row >> 7, r = row & 127;
            uint32_t c16 = (uint32_t)(lane >> 1);
            uint32_t soff = (uint32_t)r * 256u + swz((uint32_t)(r & 7), c16) * 16u
                            + (uint32_t)(lane & 1) * 8u;
            *(uint2*)((char*)g_hf + (size_t)blk * TILEB + soff) = hu;
            if (lane == 0) {
                float px = pos[3 * row], py = pos[3 * row + 1], pz = pos[3 * row + 2];
                g_pos4[row] = make_float4(px, py, pz, px * px + py * py + pz * pz);
            }
        }
    }
    grid_barrier(tid);

    // ================= phase 1: tile pairs =================
    {
        const int p0 = (int)((long long)blockIdx.x * NCTA / G);
        const int p1 = (int)((long long)(blockIdx.x + 1) * NCTA / G);
        if (p0 < p1) {
            int I = 0, t = p0;
            while (t >= NBLK - I) { t -= NBLK - I; I++; }
            int J = I + t;

            uint32_t aAddr[4], axr[4];
            #pragma unroll
            for (int mt = 0; mt < 4; mt++) {
                uint32_t r = (uint32_t)(warpRow * 64 + mt * 16 + (lane & 15));
                aAddr[mt] = sbase + ASM + r * 256u;
                axr[mt]   = r & 7u;
            }
            const uint32_t aSel = (uint32_t)((lane >> 4) & 1);
            uint32_t bOff[2], bxr[2];
            #pragma unroll
            for (int ntp = 0; ntp < 2; ntp++) {
                uint32_t n = (uint32_t)(warpCol * 32 + ntp * 16 + ((lane >> 4) & 1) * 8 + (lane & 7));
                bOff[ntp] = n * 256u;
                bxr[ntp]  = n & 7u;
            }
            const uint32_t bSel = (uint32_t)((lane >> 3) & 1);

            load_tile16(sbase + ASM, I, tid);
            load_tile16(sbase + BBUF(0), J, tid);
            CP_COMMIT();

            int buf = 0;
            for (int p = p0; p < p1; p++) {
                int nI = I, nJ = J + 1;
                if (nJ == NBLK) { nI = I + 1; nJ = nI; }
                const bool havenext = (p + 1 < p1);
                const bool nextSame = havenext && (nI == I);

                CP_WAIT0();
                __syncthreads();

                if (nextSame) {
                    load_tile16(sbase + BBUF(buf ^ 1), nJ, tid);
                    CP_COMMIT();
                }

                const uint32_t baseB = sbase + BBUF(buf);

                float acc[4][4][4];
                #pragma unroll
                for (int mt = 0; mt < 4; mt++)
                    #pragma unroll
                    for (int nt = 0; nt < 4; nt++)
                        #pragma unroll
                        for (int c = 0; c < 4; c++) acc[mt][nt][c] = 0.f;

                #pragma unroll 2
                for (int step = 0; step < 8; step++) {
                    const uint32_t c16a = (uint32_t)(2 * step) + aSel;
                    const uint32_t c16b = (uint32_t)(2 * step) + bSel;
                    uint32_t bh[2][4], af[4][4];
                    #pragma unroll
                    for (int ntp = 0; ntp < 2; ntp++) {
                        uint32_t sw = swz(bxr[ntp], c16b) << 4;
                        LDSM4(bh[ntp][0], bh[ntp][1], bh[ntp][2], bh[ntp][3], baseB + bOff[ntp] + sw);
                    }
                    #pragma unroll
                    for (int mt = 0; mt < 4; mt++) {
                        uint32_t sw = swz(axr[mt], c16a) << 4;
                        LDSM4(af[mt][0], af[mt][1], af[mt][2], af[mt][3], aAddr[mt] + sw);
                    }
                    #pragma unroll
                    for (int mt = 0; mt < 4; mt++)
                        #pragma unroll
                        for (int nt = 0; nt < 4; nt++)
                            MMA16816(acc[mt][nt], af[mt], bh[nt >> 1][(nt & 1) * 2], bh[nt >> 1][(nt & 1) * 2 + 1]);
                }

                __syncthreads();

                if (havenext && !nextSame) {
                    load_tile16(sbase + ASM, nI, tid);
                    load_tile16(sbase + BBUF(buf ^ 1), nJ, tid);
                    CP_COMMIT();
                }

                // ---- epilogue ----
                const int rowBase = I * 128, colBase0 = J * 128;
                const bool diag = (I == J);
                float cse[8];
                unsigned long long cpk[8];
                #pragma unroll
                for (int i = 0; i < 8; i++) { cse[i] = 0.f; cpk[i] = 0ull; }
                float4 pb[8];
                #pragma unroll
                for (int nt = 0; nt < 4; nt++)
                    #pragma unroll
                    for (int ce = 0; ce < 2; ce++)
                        pb[nt * 2 + ce] = __ldg(&g_pos4[colBase0 + warpCol * 32 + nt * 8 + (lane & 3) * 2 + ce]);

                #pragma unroll
                for (int mt = 0; mt < 4; mt++) {
                    #pragma unroll
                    for (int rs = 0; rs < 2; rs++) {
                        const int gi = rowBase + warpRow * 64 + mt * 16 + (lane >> 2) + rs * 8;
                        const float4 A = __ldg(&g_pos4[gi]);
                        const float nAx = -2.0f * A.x, nAy = -2.0f * A.y, nAz = -2.0f * A.z;
                        float a_se = 0.f;
                        unsigned long long a_pk = 0ull;
                        if (!diag) {
                            #pragma unroll
                            for (int nt = 0; nt < 4; nt++) {
                                #pragma unroll
                                for (int ce = 0; ce < 2; ce++) {
                                    float sim = acc[mt][nt][rs * 2 + ce];
                                    float e, arg = fmaf(sim, TENLOG2E, -TENLOG2E);
                                    EX2(e, arg);
                                    float4 B = pb[nt * 2 + ce];
                                    float d2 = fmaf(nAx, B.x, fmaf(nAy, B.y, fmaf(nAz, B.z, A.w + B.w)));
                                    unsigned long long pk;
                                    PACK2(pk, sim, 1.0f);
                                    pk = (d2 < EPS2) ? pk : 0ull;
                                    a_se += e;  ADD2(a_pk, pk);
                                    int ci = nt * 2 + ce;
                                    cse[ci] += e;  ADD2(cpk[ci], pk);
                                }
                            }
                        } else {
                            #pragma unroll
                            for (int nt = 0; nt < 4; nt++) {
                                #pragma unroll
                                for (int ce = 0; ce < 2; ce++) {
                                    float sim = acc[mt][nt][rs * 2 + ce];
                                    int j = colBase0 + warpCol * 32 + nt * 8 + (lane & 3) * 2 + ce;
                                    float e, arg = fmaf(sim, TENLOG2E, -TENLOG2E);
                                    EX2(e, arg);
                                    float4 B = pb[nt * 2 + ce];
                                    float d2 = fmaf(nAx, B.x, fmaf(nAy, B.y, fmaf(nAz, B.z, A.w + B.w)));
                                    bool self = (gi == j);
                                    float ev = self ? 0.0f : e;
                                    unsigned long long pk;
                                    PACK2(pk, sim, 1.0f);
                                    pk = ((d2 < EPS2) && !self) ? pk : 0ull;
                                    a_se += ev;  ADD2(a_pk, pk);
                                    int ci = nt * 2 + ce;
                                    cse[ci] += ev;  ADD2(cpk[ci], pk);
                                }
                            }
                        }
                        // row reduce over the 4 lanes (lane&3) sharing this row (FIXED)
                        {
                            unsigned long long s2 = __shfl_down_sync(0xffffffffu, a_pk, 2, 4);
                            ADD2(a_pk, s2);
                            unsigned long long s1 = __shfl_down_sync(0xffffffffu, a_pk, 1, 4);
                            ADD2(a_pk, s1);
                            a_se += __shfl_down_sync(0xffffffffu, a_se, 2, 4);
                            a_se += __shfl_down_sync(0xffffffffu, a_se, 1, 4);
                        }
                        if ((lane & 3) == 0) {
                            int rl = mt * 16 + rs * 8 + (lane >> 2);
                            float sp, ct;
                            UNPACK2(sp, ct, a_pk);
                            rbuf_se[wid * 64 + rl] = a_se;
                            rbuf_sp[wid * 64 + rl] = sp;
                            rbuf_ct[wid * 64 + rl] = ct;
                        }
                    }
                }

                // col reduce: 8 lanes (lane>>2) share each column
                #pragma unroll
                for (int ci = 0; ci < 8; ci++) {
                    float a = cse[ci];
                    unsigned long long pk = cpk[ci];
                    #pragma unroll
                    for (int o = 16; o >= 4; o >>= 1) {
                        a += __shfl_down_sync(0xffffffffu, a, o);
                        unsigned long long s = __shfl_down_sync(0xffffffffu, pk, o);
                        ADD2(pk, s);
                    }
                    if (lane < 4) {
                        int cl = (ci >> 1) * 8 + lane * 2 + (ci & 1);
                        float sp, ct;
                        UNPACK2(sp, ct, pk);
                        cbuf_se[wid * 32 + cl] = a;
                        cbuf_sp[wid * 32 + cl] = sp;
                        cbuf_ct[wid * 32 + cl] = ct;
                    }
                }
                __syncthreads();

                const int slot = p * 128;
                if (tid < 128) {
                    int half = tid >> 6, loc = tid & 63;
                    float a = 0.f, b = 0.f, c = 0.f;
                    #pragma unroll
                    for (int wc = 0; wc < 4; wc++) {
                        int w = half * 4 + wc;
                        a += rbuf_se[w * 64 + loc];
                        b += rbuf_sp[w * 64 + loc];
                        c += rbuf_ct[w * 64 + loc];
                    }
                    g_dse[slot + tid] = a; g_dsp[slot + tid] = b; g_dct[slot + tid] = c;
                } else if (!diag) {
                    int tcl = tid - 128, wc = tcl >> 5, c5 = tcl & 31;
                    float a = cbuf_se[wc * 32 + c5] + cbuf_se[(4 + wc) * 32 + c5];
                    float b = cbuf_sp[wc * 32 + c5] + cbuf_sp[(4 + wc) * 32 + c5];
                    float c = cbuf_ct[wc * 32 + c5] + cbuf_ct[(4 + wc) * 32 + c5];
                    g_tse[slot + tcl] = a; g_tsp[slot + tcl] = b; g_tct[slot + tcl] = c;
                }

                I = nI; J = nJ; buf ^= 1;
            }
        }
    }
    grid_barrier(tid);

    // ================= phase 2: final reduction (first 256 CTAs) =================
    if (blockIdx.x < 256) {
        float* s_se = (float*)(smem + RED);        // [8][32]
        float* s_sp = s_se + 256;
        float* s_ct = s_sp + 256;
        int*   s_last = (int*)(s_ct + 256);
        const int al = tid & 31, sg = tid >> 5;
        const int R = blockIdx.x >> 2;
        const int rr = ((int)blockIdx.x & 3) * 32 + al;
        const int nd = NBLK - R;
        float se = 0.f, sp = 0.f, c = 0.f;
        #pragma unroll
        for (int k = 0; k < 8; k++) {
            int s = sg * 8 + k;
            int id; const float *pse, *psp, *pct;
            if (s < nd) { id = tri_base(R) + s;        pse = g_dse; psp = g_dsp; pct = g_dct; }
            else        { int I2 = s - nd;
                          id = tri_base(I2) + (R - I2); pse = g_tse; psp = g_tsp; pct = g_tct; }
            se += __ldcg(&pse[id * 128 + rr]);
            sp += __ldcg(&psp[id * 128 + rr]);
            c  += __ldcg(&pct[id * 128 + rr]);
        }
        s_se[sg * 32 + al] = se; s_sp[sg * 32 + al] = sp; s_ct[sg * 32 + al] = c;
        __syncthreads();
        if (tid < 32) {
            float a = 0.f, b = 0.f, cc = 0.f;
            #pragma unroll
            for (int g = 0; g < 8; g++) {
                a += s_se[g * 32 + tid]; b += s_sp[g * 32 + tid]; cc += s_ct[g * 32 + tid];
            }
            float lse = logf(a) + 10.0f;
            float L = 0.f, V = 0.f;
            if (cc > 0.0f) { L = -(10.0f * b - cc * lse) / cc; V = 1.0f; }
            #pragma unroll
            for (int o = 16; o; o >>= 1) {
                L += __shfl_down_sync(0xffffffffu, L, o);
                V += __shfl_down_sync(0xffffffffu, V, o);
            }
            if (tid == 0) { g_partL[blockIdx.x] = L; g_partV[blockIdx.x] = V; }
        }
        __threadfence();
        __syncthreads();
        if (tid == 0) *s_last = (atomicAdd(&g_done, 1) == 255);
        __syncthreads();
        if (*s_last) {
            float a = __ldcg(&g_partL[tid]), b = __ldcg(&g_partV[tid]);
            #pragma unroll
            for (int o = 16; o; o >>= 1) {
                a += __shfl_down_sync(0xffffffffu, a, o);
                b += __shfl_down_sync(0xffffffffu, b, o);
            }
            if ((tid & 31) == 0) { s_se[tid >> 5] = a; s_sp[tid >> 5] = b; }
            __syncthreads();
            if (tid == 0) {
                float ta = 0.f, tb = 0.f;
                #pragma unroll
                for (int w = 0; w < 8; w++) { ta += s_se[w]; tb += s_sp[w]; }
                out[0] = ta / fmaxf(tb, 1.0f);
            }
        }
    }
}

// ---------------- launch ----------------
extern "C" void kernel_launch(void* const* d_in, const int* in_sizes, int n_in,
                              void* d_out, int out_size) {
    const float* h   = (const float*)d_in[0];
    const float* pos = (const float*)d_in[1];
    if (n_in >= 2 && in_sizes[0] < in_sizes[1]) {
        const float* t = h; h = pos; pos = t;
    }
    float* out = (float*)d_out;

    int dev = 0, sms = 148;
    cudaGetDevice(&dev);
    cudaDeviceGetAttribute(&sms, cudaDevAttrMultiProcessorCount, dev);
    int G = 2 * sms;                      // all CTAs resident (occ 2 guaranteed)

    cudaFuncSetAttribute(fused_kernel, cudaFuncAttributeMaxDynamicSharedMemorySize, SMEM_REQ);
    fused_kernel<<<G, 256, SMEM_REQ>>>(h, pos, out);
}